// round 12
// baseline (speedup 1.0000x reference)
#include <cuda_runtime.h>
#include <cuda_bf16.h>
#include <cstdint>
#include <math.h>

#define HDIM 1024
#define FDIM 2048
#define NEXP 8
#define NGRP 9
#define NTOK 4096
#define NROWS_ROUTED 8192
#define NROWS_TOTAL 12288
#define WELEMS ((size_t)NGRP * FDIM * HDIM)

typedef unsigned long long u64;
typedef uint32_t u32;

// ---------------- scratch (static device globals; no allocation) ----------------
__device__ __align__(256) __nv_bfloat16 g_x_hi[(size_t)NTOK * HDIM];
__device__ __align__(256) __nv_bfloat16 g_x_lo[(size_t)NTOK * HDIM];
__device__ __align__(256) __nv_bfloat16 g_wg_hi[WELEMS];
__device__ __align__(256) __nv_bfloat16 g_wg_lo[WELEMS];
__device__ __align__(256) __nv_bfloat16 g_wu_hi[WELEMS];
__device__ __align__(256) __nv_bfloat16 g_wu_lo[WELEMS];
__device__ __align__(256) __nv_bfloat16 g_wd_hi[WELEMS];
__device__ __align__(256) __nv_bfloat16 g_wd_lo[WELEMS];
__device__ __align__(256) __nv_bfloat16 g_act_hi[(size_t)NROWS_TOTAL * FDIM];
__device__ __align__(256) __nv_bfloat16 g_act_lo[(size_t)NROWS_TOTAL * FDIM];
__device__ __align__(256) float g_t1[(size_t)NROWS_TOTAL * FDIM];  // mma: gate pre-act | fb: fused act
__device__ __align__(256) float g_t2[(size_t)NROWS_TOTAL * FDIM];  // mma: up pre-act
__device__ __align__(256) float g_y[(size_t)NROWS_TOTAL * HDIM];
__device__ int   g_rowtok[NROWS_TOTAL];
__device__ int   g_tokpos[NTOK * 2];
__device__ float g_tokw[NTOK * 2];
__device__ float g_imp[NEXP];
__device__ int   g_load[NEXP];
__device__ float g_z2;
__device__ int   g_cnt[NEXP];
__device__ int   g_off[NEXP];
__device__ int   g_cur[NEXP];
__device__ int   g_flag;   // 0 = mma path verified OK, 1 = fall back to FFMA2 path

// ---------------- mma.sync (the instruction under test) ----------------
__device__ __forceinline__ void mma16816(float* c, const u32* a, const u32* b) {
    asm volatile("mma.sync.aligned.m16n8k16.row.col.f32.bf16.bf16.f32 "
        "{%0,%1,%2,%3}, {%4,%5,%6,%7}, {%8,%9}, {%0,%1,%2,%3};"
        : "+f"(c[0]), "+f"(c[1]), "+f"(c[2]), "+f"(c[3])
        : "r"(a[0]), "r"(a[1]), "r"(a[2]), "r"(a[3]), "r"(b[0]), "r"(b[1]));
}

// ---------------- packed f32x2 helpers (proven R6 path) ----------------
__device__ __forceinline__ u64 pack2(float x, float y) {
    u64 r; asm("mov.b64 %0, {%1, %2};" : "=l"(r) : "f"(x), "f"(y)); return r;
}
__device__ __forceinline__ u64 ffma2(u64 a, u64 b, u64 c) {
    u64 d; asm("fma.rn.f32x2 %0, %1, %2, %3;" : "=l"(d) : "l"(a), "l"(b), "l"(c)); return d;
}
__device__ __forceinline__ float2 unpack2(u64 v) {
    float2 f; asm("mov.b64 {%0, %1}, %2;" : "=f"(f.x), "=f"(f.y) : "l"(v)); return f;
}

// ---------------- init ----------------
__global__ void init_kernel() {
    int t = threadIdx.x;
    if (t < NEXP) { g_imp[t] = 0.f; g_load[t] = 0; g_cnt[t] = 0; }
    if (t == NEXP) { g_z2 = 0.f; g_flag = 0; }
}

// ---------------- hi/lo split conversion ----------------
__global__ void conv_split_kernel(const float* __restrict__ se, const float* __restrict__ ssh,
                                  size_t n_e, size_t n_total,
                                  __nv_bfloat16* __restrict__ hi, __nv_bfloat16* __restrict__ lo) {
    size_t i = ((size_t)blockIdx.x * blockDim.x + threadIdx.x) * 4;
    if (i >= n_total) return;
    float4 v = (i < n_e) ? *(const float4*)(se + i) : *(const float4*)(ssh + (i - n_e));
    float a[4] = {v.x, v.y, v.z, v.w};
    __nv_bfloat16 h[4], l[4];
    #pragma unroll
    for (int j = 0; j < 4; j++) {
        h[j] = __float2bfloat16(a[j]);
        l[j] = __float2bfloat16(a[j] - __bfloat162float(h[j]));
    }
    *(__nv_bfloat162*)(hi + i)     = __halves2bfloat162(h[0], h[1]);
    *(__nv_bfloat162*)(hi + i + 2) = __halves2bfloat162(h[2], h[3]);
    *(__nv_bfloat162*)(lo + i)     = __halves2bfloat162(l[0], l[1]);
    *(__nv_bfloat162*)(lo + i + 2) = __halves2bfloat162(l[2], l[3]);
}

// ---------------- router ----------------
__global__ void router_kernel(const float* __restrict__ x, const float* __restrict__ wr) {
    int n = blockIdx.x;
    int tid = threadIdx.x;
    int w = tid >> 5, lane = tid & 31;
    const float* xr = x + (size_t)n * HDIM;
    const float* we = wr + (size_t)w * HDIM;
    float s = 0.f;
    for (int j = lane; j < HDIM; j += 32) s += xr[j] * we[j];
    #pragma unroll
    for (int o = 16; o; o >>= 1) s += __shfl_xor_sync(0xffffffffu, s, o);
    __shared__ float lg[NEXP];
    if (lane == 0) lg[w] = s;
    __syncthreads();
    if (tid == 0) {
        float l[NEXP], p[NEXP];
        float m = -1e30f;
        #pragma unroll
        for (int e = 0; e < NEXP; e++) { l[e] = lg[e]; m = fmaxf(m, l[e]); }
        float se = 0.f;
        #pragma unroll
        for (int e = 0; e < NEXP; e++) { p[e] = expf(l[e] - m); se += p[e]; }
        float inv = 1.f / se;
        #pragma unroll
        for (int e = 0; e < NEXP; e++) { p[e] *= inv; atomicAdd(&g_imp[e], p[e]); }
        float z = m + logf(se);
        atomicAdd(&g_z2, z * z);
        int i1 = 0;
        #pragma unroll
        for (int e = 1; e < NEXP; e++) if (p[e] > p[i1]) i1 = e;
        int i2 = -1;
        #pragma unroll
        for (int e = 0; e < NEXP; e++) {
            if (e == i1) continue;
            if (i2 < 0 || p[e] > p[i2]) i2 = e;
        }
        float denom = p[i1] + p[i2] + 1e-9f;
        g_tokw[n * 2 + 0] = p[i1] / denom;
        g_tokw[n * 2 + 1] = p[i2] / denom;
        atomicAdd(&g_load[i1], 1);
        atomicAdd(&g_cnt[i1], 1);
        atomicAdd(&g_cnt[i2], 1);
        g_tokpos[n * 2 + 0] = i1;
        g_tokpos[n * 2 + 1] = i2;
    }
}

__global__ void prefix_kernel() {
    int o = 0;
    for (int e = 0; e < NEXP; e++) { g_off[e] = o; o += g_cnt[e]; g_cur[e] = 0; }
}

__global__ void scatter_kernel() {
    int n = blockIdx.x * blockDim.x + threadIdx.x;
    if (n < NTOK) {
        #pragma unroll
        for (int k = 0; k < 2; k++) {
            int e = g_tokpos[n * 2 + k];
            int p = g_off[e] + atomicAdd(&g_cur[e], 1);
            g_rowtok[p] = n;
            g_tokpos[n * 2 + k] = p;
        }
        g_rowtok[NROWS_ROUTED + n] = n;
    }
}

// =======================================================================
// mma.sync grouped GEMM (path under test), BM=64 BN=64 BK=32, static smem
// =======================================================================
#define SMSTRIDE 40

template<int K, bool GATHER>
__global__ void __launch_bounds__(256)
gemm_mma_kernel(const __nv_bfloat16* __restrict__ Ah, const __nv_bfloat16* __restrict__ Al,
                const __nv_bfloat16* __restrict__ Wh, const __nv_bfloat16* __restrict__ Wl,
                float* __restrict__ C, int Ntot, int guarded) {
    if (guarded && g_flag != 0) return;
    __shared__ __nv_bfloat16 sAh[64][SMSTRIDE], sAl[64][SMSTRIDE];
    __shared__ __nv_bfloat16 sBh[64][SMSTRIDE], sBl[64][SMSTRIDE];

    const int g = blockIdx.y;
    int off, cnt;
    if (g < NEXP) { off = g_off[g]; cnt = g_cnt[g]; }
    else          { off = NROWS_ROUTED; cnt = NTOK; }
    const int row0 = blockIdx.x * 64;
    if (row0 >= cnt) return;
    const int n0 = blockIdx.z * 64;

    const int tid = threadIdx.x, wid = tid >> 5, lane = tid & 31;

    const int lrow = tid >> 2, lq = tid & 3;
    const __nv_bfloat16 *aph, *apl;
    {
        int rr = row0 + lrow;
        int rc = (rr < cnt) ? rr : (cnt - 1);
        if (GATHER) {
            int tok = g_rowtok[off + rc];
            aph = Ah + (size_t)tok * K + lq * 8;
            apl = Al + (size_t)tok * K + lq * 8;
        } else {
            aph = Ah + (size_t)(off + rc) * K + lq * 8;
            apl = Al + (size_t)(off + rc) * K + lq * 8;
        }
    }
    const __nv_bfloat16* wph = Wh + (size_t)g * Ntot * K + (size_t)(n0 + lrow) * K + lq * 8;
    const __nv_bfloat16* wpl = Wl + (size_t)g * Ntot * K + (size_t)(n0 + lrow) * K + lq * 8;

    const int wm = wid >> 2, wn = wid & 3;
    const int gid = lane >> 2, tig = lane & 3;

    float acc[2][2][4];
    #pragma unroll
    for (int mi = 0; mi < 2; mi++)
        #pragma unroll
        for (int ni = 0; ni < 2; ni++)
            #pragma unroll
            for (int q = 0; q < 4; q++) acc[mi][ni][q] = 0.f;

    int4 rah = *(const int4*)(aph);
    int4 ral = *(const int4*)(apl);
    int4 rbh = *(const int4*)(wph);
    int4 rbl = *(const int4*)(wpl);

    const int NK = K / 32;
    for (int c = 0; c < NK; c++) {
        __syncthreads();
        *(int4*)&sAh[lrow][lq * 8] = rah;
        *(int4*)&sAl[lrow][lq * 8] = ral;
        *(int4*)&sBh[lrow][lq * 8] = rbh;
        *(int4*)&sBl[lrow][lq * 8] = rbl;
        __syncthreads();
        if (c + 1 < NK) {
            int kt = (c + 1) * 32;
            rah = *(const int4*)(aph + kt);
            ral = *(const int4*)(apl + kt);
            rbh = *(const int4*)(wph + kt);
            rbl = *(const int4*)(wpl + kt);
        }
        #pragma unroll
        for (int ks = 0; ks < 2; ks++) {
            const int kk = ks * 16 + tig * 2;
            u32 a_h[2][4], a_l[2][4];
            #pragma unroll
            for (int mi = 0; mi < 2; mi++) {
                int rb = wm * 32 + mi * 16 + gid;
                a_h[mi][0] = *(const u32*)&sAh[rb][kk];
                a_h[mi][1] = *(const u32*)&sAh[rb + 8][kk];
                a_h[mi][2] = *(const u32*)&sAh[rb][kk + 8];
                a_h[mi][3] = *(const u32*)&sAh[rb + 8][kk + 8];
                a_l[mi][0] = *(const u32*)&sAl[rb][kk];
                a_l[mi][1] = *(const u32*)&sAl[rb + 8][kk];
                a_l[mi][2] = *(const u32*)&sAl[rb][kk + 8];
                a_l[mi][3] = *(const u32*)&sAl[rb + 8][kk + 8];
            }
            u32 b_h[2][2], b_l[2][2];
            #pragma unroll
            for (int ni = 0; ni < 2; ni++) {
                int cb = wn * 16 + ni * 8 + gid;
                b_h[ni][0] = *(const u32*)&sBh[cb][kk];
                b_h[ni][1] = *(const u32*)&sBh[cb][kk + 8];
                b_l[ni][0] = *(const u32*)&sBl[cb][kk];
                b_l[ni][1] = *(const u32*)&sBl[cb][kk + 8];
            }
            #pragma unroll
            for (int mi = 0; mi < 2; mi++)
                #pragma unroll
                for (int ni = 0; ni < 2; ni++) {
                    mma16816(acc[mi][ni], a_h[mi], b_h[ni]);
                    mma16816(acc[mi][ni], a_h[mi], b_l[ni]);
                    mma16816(acc[mi][ni], a_l[mi], b_h[ni]);
                }
        }
    }

    #pragma unroll
    for (int mi = 0; mi < 2; mi++)
        #pragma unroll
        for (int ni = 0; ni < 2; ni++) {
            int row = row0 + wm * 32 + mi * 16 + gid;
            int col = n0 + wn * 16 + ni * 8 + tig * 2;
            if (row < cnt) {
                float* o = C + (size_t)(off + row) * Ntot + col;
                o[0] = acc[mi][ni][0]; o[1] = acc[mi][ni][1];
            }
            if (row + 8 < cnt) {
                float* o = C + (size_t)(off + row + 8) * Ntot + col;
                o[0] = acc[mi][ni][2]; o[1] = acc[mi][ni][3];
            }
        }
}

// ---------------- check 1: spot-verify t1/t2 against fp32 scalar dots ----------------
__global__ void check_gu_kernel(const float* __restrict__ x,
                                const float* __restrict__ weg, const float* __restrict__ wshg,
                                const float* __restrict__ weu, const float* __restrict__ wshu) {
    int t = threadIdx.x;  // 64 threads
    // shared-expert group (always 4096 rows)
    {
        int r = (t * 61) & 4095;
        int cc = (t * 127) & 2047;
        int tok = g_rowtok[NROWS_ROUTED + r];
        const float* xr = x + (size_t)tok * HDIM;
        const float* wg = wshg + (size_t)cc * HDIM;
        const float* wu = wshu + (size_t)cc * HDIM;
        float sg = 0.f, su = 0.f;
        for (int h = 0; h < HDIM; h++) { sg += xr[h] * wg[h]; su += xr[h] * wu[h]; }
        float tg = g_t1[(size_t)(NROWS_ROUTED + r) * FDIM + cc];
        float tu = g_t2[(size_t)(NROWS_ROUTED + r) * FDIM + cc];
        if (fabsf(tg - sg) > 2e-2f * fmaxf(fabsf(sg), 0.5f) ||
            fabsf(tu - su) > 2e-2f * fmaxf(fabsf(su), 0.5f)) atomicOr(&g_flag, 1);
    }
    // routed groups (checks the gather path)
    if (t < NEXP && g_cnt[t] > 0) {
        int off = g_off[t];
        int cc = (t * 251) & 2047;
        int tok = g_rowtok[off];
        const float* xr = x + (size_t)tok * HDIM;
        const float* wg = weg + (size_t)t * FDIM * HDIM + (size_t)cc * HDIM;
        float sg = 0.f;
        for (int h = 0; h < HDIM; h++) sg += xr[h] * wg[h];
        float tg = g_t1[(size_t)off * FDIM + cc];
        if (fabsf(tg - sg) > 2e-2f * fmaxf(fabsf(sg), 0.5f)) atomicOr(&g_flag, 1);
    }
}

// ---------------- silu(t1)*t2 -> act hi/lo (mma path only) ----------------
__global__ void silu_split_kernel() {
    if (g_flag != 0) return;
    size_t i = ((size_t)blockIdx.x * blockDim.x + threadIdx.x) * 4;
    if (i >= (size_t)NROWS_TOTAL * FDIM) return;
    float4 gv = *(const float4*)(g_t1 + i);
    float4 uv = *(const float4*)(g_t2 + i);
    float gg[4] = {gv.x, gv.y, gv.z, gv.w};
    float uu[4] = {uv.x, uv.y, uv.z, uv.w};
    __nv_bfloat16 h[4], l[4];
    #pragma unroll
    for (int j = 0; j < 4; j++) {
        float s = uu[j] * gg[j] / (1.f + __expf(-gg[j]));
        h[j] = __float2bfloat16(s);
        l[j] = __float2bfloat16(s - __bfloat162float(h[j]));
    }
    *(__nv_bfloat162*)(g_act_hi + i)     = __halves2bfloat162(h[0], h[1]);
    *(__nv_bfloat162*)(g_act_hi + i + 2) = __halves2bfloat162(h[2], h[3]);
    *(__nv_bfloat162*)(g_act_lo + i)     = __halves2bfloat162(l[0], l[1]);
    *(__nv_bfloat162*)(g_act_lo + i + 2) = __halves2bfloat162(l[2], l[3]);
}

// ---------------- check 2: spot-verify g_y from the mma down GEMM ----------------
__global__ void check_down_kernel(const float* __restrict__ wed, const float* __restrict__ wshd) {
    if (g_flag != 0) return;
    int t = threadIdx.x;  // 64 threads
    {
        int r = (t * 61) & 4095;
        int cc = (t * 127) & 1023;
        const __nv_bfloat16* ah = g_act_hi + (size_t)(NROWS_ROUTED + r) * FDIM;
        const __nv_bfloat16* al = g_act_lo + (size_t)(NROWS_ROUTED + r) * FDIM;
        const float* wd = wshd + (size_t)cc * FDIM;
        float s = 0.f;
        for (int f = 0; f < FDIM; f++)
            s += (__bfloat162float(ah[f]) + __bfloat162float(al[f])) * wd[f];
        float ty = g_y[(size_t)(NROWS_ROUTED + r) * HDIM + cc];
        if (fabsf(ty - s) > 2e-2f * fmaxf(fabsf(s), 0.1f)) atomicOr(&g_flag, 1);
    }
    if (t < NEXP && g_cnt[t] > 0) {
        int off = g_off[t];
        int cc = (t * 163) & 1023;
        const __nv_bfloat16* ah = g_act_hi + (size_t)off * FDIM;
        const __nv_bfloat16* al = g_act_lo + (size_t)off * FDIM;
        const float* wd = wed + (size_t)t * HDIM * FDIM + (size_t)cc * FDIM;
        float s = 0.f;
        for (int f = 0; f < FDIM; f++)
            s += (__bfloat162float(ah[f]) + __bfloat162float(al[f])) * wd[f];
        float ty = g_y[(size_t)off * HDIM + cc];
        if (fabsf(ty - s) > 2e-2f * fmaxf(fabsf(s), 0.1f)) atomicOr(&g_flag, 1);
    }
}

// =======================================================================
// FALLBACK: proven R6 FFMA2 kernels (bit-identical logic; + flag guard)
// fb_gu writes fused act (fp32) into g_t1; fb_down reads g_t1 -> g_y.
// =======================================================================
#define BM 128
#define BN 64
#define BK 16

__global__ void __launch_bounds__(256, 2)
fb_gu_kernel(const float* __restrict__ x,
             const float* __restrict__ weg, const float* __restrict__ wshg,
             const float* __restrict__ weu, const float* __restrict__ wshu) {
    if (g_flag == 0) return;
    const int g = blockIdx.y;
    int off, cnt;
    if (g < NEXP) { off = g_off[g]; cnt = g_cnt[g]; }
    else          { off = NROWS_ROUTED; cnt = NTOK; }
    const int row0 = blockIdx.x * BM;
    if (row0 >= cnt) return;

    const float* Bg = (g < NEXP) ? (weg + (size_t)g * ((size_t)FDIM * HDIM)) : wshg;
    const float* Bu = (g < NEXP) ? (weu + (size_t)g * ((size_t)FDIM * HDIM)) : wshu;
    const int n0 = blockIdx.z * BN;

    __shared__ float As [BK][BM + 4];
    __shared__ float Bgs[BK][BN + 4];
    __shared__ float Bus[BK][BN + 4];
    __shared__ const float* Arow[BM];

    const int tid = threadIdx.x;
    if (tid < BM) {
        int r = row0 + tid;
        int rc = (r < cnt) ? r : (cnt - 1);
        Arow[tid] = x + (size_t)g_rowtok[off + rc] * HDIM;
    }
    __syncthreads();

    u64 accg[8][2], accu[8][2];
    #pragma unroll
    for (int i = 0; i < 8; i++) { accg[i][0] = accg[i][1] = 0ull; accu[i][0] = accu[i][1] = 0ull; }

    const int tr = tid >> 4, tc = tid & 15;
    const int lm = tid >> 2, lk = tid & 3;
    const int bn = tid >> 2, bk = tid & 3;

    const float* aptr0 = Arow[lm]      + lk * 4;
    const float* aptr1 = Arow[lm + 64] + lk * 4;

    for (int kt = 0; kt < HDIM; kt += BK) {
        {
            float4 v = *(const float4*)(aptr0 + kt);
            As[lk * 4 + 0][lm] = v.x; As[lk * 4 + 1][lm] = v.y;
            As[lk * 4 + 2][lm] = v.z; As[lk * 4 + 3][lm] = v.w;
            float4 w = *(const float4*)(aptr1 + kt);
            As[lk * 4 + 0][lm + 64] = w.x; As[lk * 4 + 1][lm + 64] = w.y;
            As[lk * 4 + 2][lm + 64] = w.z; As[lk * 4 + 3][lm + 64] = w.w;
        }
        {
            size_t boff = (size_t)(n0 + bn) * HDIM + kt + bk * 4;
            float4 vg = *(const float4*)(Bg + boff);
            Bgs[bk * 4 + 0][bn] = vg.x; Bgs[bk * 4 + 1][bn] = vg.y;
            Bgs[bk * 4 + 2][bn] = vg.z; Bgs[bk * 4 + 3][bn] = vg.w;
            float4 vu = *(const float4*)(Bu + boff);
            Bus[bk * 4 + 0][bn] = vu.x; Bus[bk * 4 + 1][bn] = vu.y;
            Bus[bk * 4 + 2][bn] = vu.z; Bus[bk * 4 + 3][bn] = vu.w;
        }
        __syncthreads();
        #pragma unroll
        for (int kk = 0; kk < BK; kk++) {
            float4 a0 = *(const float4*)&As[kk][tr * 8];
            float4 a1 = *(const float4*)&As[kk][tr * 8 + 4];
            ulonglong2 bg2 = *(const ulonglong2*)&Bgs[kk][tc * 4];
            ulonglong2 bu2 = *(const ulonglong2*)&Bus[kk][tc * 4];
            u64 a2[8];
            a2[0] = pack2(a0.x, a0.x); a2[1] = pack2(a0.y, a0.y);
            a2[2] = pack2(a0.z, a0.z); a2[3] = pack2(a0.w, a0.w);
            a2[4] = pack2(a1.x, a1.x); a2[5] = pack2(a1.y, a1.y);
            a2[6] = pack2(a1.z, a1.z); a2[7] = pack2(a1.w, a1.w);
            #pragma unroll
            for (int i = 0; i < 8; i++) {
                accg[i][0] = ffma2(a2[i], bg2.x, accg[i][0]);
                accg[i][1] = ffma2(a2[i], bg2.y, accg[i][1]);
                accu[i][0] = ffma2(a2[i], bu2.x, accu[i][0]);
                accu[i][1] = ffma2(a2[i], bu2.y, accu[i][1]);
            }
        }
        __syncthreads();
    }

    #pragma unroll
    for (int i = 0; i < 8; i++) {
        int r = row0 + tr * 8 + i;
        if (r < cnt) {
            float* o = g_t1 + (size_t)(off + r) * FDIM + n0 + tc * 4;
            #pragma unroll
            for (int jp = 0; jp < 2; jp++) {
                float2 gg = unpack2(accg[i][jp]);
                float2 uu = unpack2(accu[i][jp]);
                o[jp * 2 + 0] = (gg.x / (1.f + __expf(-gg.x))) * uu.x;
                o[jp * 2 + 1] = (gg.y / (1.f + __expf(-gg.y))) * uu.y;
            }
        }
    }
}

__global__ void __launch_bounds__(256, 2)
fb_down_kernel(const float* __restrict__ wed, const float* __restrict__ wshd) {
    if (g_flag == 0) return;
    const int g = blockIdx.y;
    int off, cnt;
    if (g < NEXP) { off = g_off[g]; cnt = g_cnt[g]; }
    else          { off = NROWS_ROUTED; cnt = NTOK; }
    const int row0 = blockIdx.x * BM;
    if (row0 >= cnt) return;

    const float* Bp = (g < NEXP) ? (wed + (size_t)g * ((size_t)HDIM * FDIM)) : wshd;
    const int n0 = blockIdx.z * BN;

    __shared__ float As[BK][BM + 4];
    __shared__ float Bs[BK][BN + 4];

    const int tid = threadIdx.x;
    const int tr = tid >> 4, tc = tid & 15;
    const int lm = tid >> 2, lk = tid & 3;
    const int bn = tid >> 2, bk = tid & 3;

    const int rA  = (row0 + lm      < cnt) ? (row0 + lm)      : (cnt - 1);
    const int rA1 = (row0 + lm + 64 < cnt) ? (row0 + lm + 64) : (cnt - 1);
    const float* a_base0 = g_t1 + (size_t)(off + rA)  * FDIM + lk * 4;
    const float* a_base1 = g_t1 + (size_t)(off + rA1) * FDIM + lk * 4;

    u64 acc[8][2];
    #pragma unroll
    for (int i = 0; i < 8; i++) { acc[i][0] = 0ull; acc[i][1] = 0ull; }

    for (int kt = 0; kt < FDIM; kt += BK) {
        {
            float4 v0 = *(const float4*)(a_base0 + kt);
            As[lk * 4 + 0][lm] = v0.x; As[lk * 4 + 1][lm] = v0.y;
            As[lk * 4 + 2][lm] = v0.z; As[lk * 4 + 3][lm] = v0.w;
            float4 v1 = *(const float4*)(a_base1 + kt);
            As[lk * 4 + 0][lm + 64] = v1.x; As[lk * 4 + 1][lm + 64] = v1.y;
            As[lk * 4 + 2][lm + 64] = v1.z; As[lk * 4 + 3][lm + 64] = v1.w;
        }
        {
            float4 v = *(const float4*)(Bp + (size_t)(n0 + bn) * FDIM + kt + bk * 4);
            Bs[bk * 4 + 0][bn] = v.x; Bs[bk * 4 + 1][bn] = v.y;
            Bs[bk * 4 + 2][bn] = v.z; Bs[bk * 4 + 3][bn] = v.w;
        }
        __syncthreads();
        #pragma unroll
        for (int kk = 0; kk < BK; kk++) {
            float4 a0 = *(const float4*)&As[kk][tr * 8];
            float4 a1 = *(const float4*)&As[kk][tr * 8 + 4];
            ulonglong2 b2 = *(const ulonglong2*)&Bs[kk][tc * 4];
            u64 a2[8];
            a2[0] = pack2(a0.x, a0.x); a2[1] = pack2(a0.y, a0.y);
            a2[2] = pack2(a0.z, a0.z); a2[3] = pack2(a0.w, a0.w);
            a2[4] = pack2(a1.x, a1.x); a2[5] = pack2(a1.y, a1.y);
            a2[6] = pack2(a1.z, a1.z); a2[7] = pack2(a1.w, a1.w);
            #pragma unroll
            for (int i = 0; i < 8; i++) {
                acc[i][0] = ffma2(a2[i], b2.x, acc[i][0]);
                acc[i][1] = ffma2(a2[i], b2.y, acc[i][1]);
            }
        }
        __syncthreads();
    }

    #pragma unroll
    for (int i = 0; i < 8; i++) {
        int r = row0 + tr * 8 + i;
        if (r < cnt) {
            float* o = g_y + (size_t)(off + r) * HDIM + n0 + tc * 4;
            float2 v0 = unpack2(acc[i][0]);
            float2 v1 = unpack2(acc[i][1]);
            o[0] = v0.x; o[1] = v0.y; o[2] = v1.x; o[3] = v1.y;
        }
    }
}

// ---------------- combine ----------------
__global__ void combine_kernel(float* __restrict__ out) {
    int n = blockIdx.x;
    int p0 = g_tokpos[n * 2], p1 = g_tokpos[n * 2 + 1];
    float w0 = g_tokw[n * 2], w1 = g_tokw[n * 2 + 1];
    const float4* ysh = (const float4*)(g_y + (size_t)(NROWS_ROUTED + n) * HDIM);
    const float4* y0  = (const float4*)(g_y + (size_t)p0 * HDIM);
    const float4* y1  = (const float4*)(g_y + (size_t)p1 * HDIM);
    float4* o = (float4*)(out + (size_t)n * HDIM);
    for (int h = threadIdx.x; h < HDIM / 4; h += blockDim.x) {
        float4 s = ysh[h], a = y0[h], b = y1[h], rr;
        rr.x = s.x + w0 * a.x + w1 * b.x;
        rr.y = s.y + w0 * a.y + w1 * b.y;
        rr.z = s.z + w0 * a.z + w1 * b.z;
        rr.w = s.w + w0 * a.w + w1 * b.w;
        o[h] = rr;
    }
}

// ---------------- aux ----------------
__global__ void aux_kernel(float* __restrict__ out, int out_size) {
    const int yelems = NTOK * HDIM;
    if (out_size <= yelems) return;
    float imp[NEXP], ld[NEXP];
    float impSum = 0.f, loadSum = 0.f;
    for (int e = 0; e < NEXP; e++) {
        imp[e] = g_imp[e]; ld[e] = (float)g_load[e];
        impSum += imp[e]; loadSum += ld[e];
    }
    float lb = 0.f;
    for (int e = 0; e < NEXP; e++)
        lb += (imp[e] / (impSum + 1e-9f)) * (ld[e] / (loadSum + 1e-9f));
    lb *= (float)NEXP;
    float z_loss = 0.001f * (g_z2 / (float)NTOK);
    out[yelems] = 0.01f * lb + z_loss;
    for (int i = yelems + 1; i < out_size; i++) out[i] = 0.f;
}

// ---------------- launch ----------------
extern "C" void kernel_launch(void* const* d_in, const int* in_sizes, int n_in,
                              void* d_out, int out_size) {
    const float* x    = (const float*)d_in[0];
    const float* wr   = (const float*)d_in[1];
    const float* wshg = (const float*)d_in[2];
    const float* wshu = (const float*)d_in[3];
    const float* wshd = (const float*)d_in[4];
    const float* weg  = (const float*)d_in[5];
    const float* weu  = (const float*)d_in[6];
    const float* wed  = (const float*)d_in[7];
    float* out = (float*)d_out;

    init_kernel<<<1, 32>>>();

    const size_t xle = (size_t)NTOK * HDIM;
    const size_t wle = WELEMS, we8 = (size_t)NEXP * FDIM * HDIM;
    conv_split_kernel<<<(int)(xle / 4 / 256), 256>>>(x, x, xle, xle, g_x_hi, g_x_lo);
    conv_split_kernel<<<(int)(wle / 4 / 256), 256>>>(weg, wshg, we8, wle, g_wg_hi, g_wg_lo);
    conv_split_kernel<<<(int)(wle / 4 / 256), 256>>>(weu, wshu, we8, wle, g_wu_hi, g_wu_lo);
    conv_split_kernel<<<(int)(wle / 4 / 256), 256>>>(wed, wshd, we8, wle, g_wd_hi, g_wd_lo);

    router_kernel<<<NTOK, 256>>>(x, wr);
    prefix_kernel<<<1, 1>>>();
    scatter_kernel<<<16, 256>>>();

    // --- mma.sync path (under test) ---
    dim3 gGU(64, NGRP, FDIM / 64);
    gemm_mma_kernel<HDIM, true><<<gGU, 256>>>(g_x_hi, g_x_lo, g_wg_hi, g_wg_lo, g_t1, FDIM, 0);
    gemm_mma_kernel<HDIM, true><<<gGU, 256>>>(g_x_hi, g_x_lo, g_wu_hi, g_wu_lo, g_t2, FDIM, 0);
    check_gu_kernel<<<1, 64>>>(x, weg, wshg, weu, wshu);

    const size_t ae = (size_t)NROWS_TOTAL * FDIM;
    silu_split_kernel<<<(int)(ae / 4 / 256), 256>>>();
    dim3 gDN(64, NGRP, HDIM / 64);
    gemm_mma_kernel<FDIM, false><<<gDN, 256>>>(g_act_hi, g_act_lo, g_wd_hi, g_wd_lo, g_y, HDIM, 1);
    check_down_kernel<<<1, 64>>>(wed, wshd);

    // --- fallback path (runs only if a check failed) ---
    dim3 fGU(NROWS_ROUTED / BM, NGRP, FDIM / BN);
    fb_gu_kernel<<<fGU, 256>>>(x, weg, wshg, weu, wshu);
    dim3 fDN(NROWS_ROUTED / BM, NGRP, HDIM / BN);
    fb_down_kernel<<<fDN, 256>>>(wed, wshd);

    combine_kernel<<<NTOK, 256>>>(out);
    aux_kernel<<<1, 1>>>(out, out_size);
}

// round 13
// speedup vs baseline: 11.4406x; 11.4406x over previous
#include <cuda_runtime.h>
#include <cstdint>
#include <math.h>

#define HDIM 1024
#define FDIM 2048
#define NEXP 8
#define NGRP 9
#define NTOK 4096
#define NROWS_ROUTED 8192
#define NROWS_TOTAL 12288

typedef unsigned long long u64;

// ---------------- scratch (static device globals; no allocation) ----------------
__device__ __align__(256) float g_act[(size_t)NROWS_TOTAL * FDIM];  // silu(gate)*up
__device__ __align__(256) float g_y[(size_t)NROWS_TOTAL * HDIM];    // down outputs
__device__ int   g_rowtok[NROWS_TOTAL];
__device__ int   g_tokpos[NTOK * 2];
__device__ float g_tokw[NTOK * 2];
__device__ float g_imp[NEXP];
__device__ int   g_load[NEXP];
__device__ float g_z2;
__device__ int   g_cnt[NEXP];
__device__ int   g_off[NEXP];
__device__ int   g_cur[NEXP];

// ---------------- packed f32x2 helpers ----------------
__device__ __forceinline__ u64 pack2(float x, float y) {
    u64 r; asm("mov.b64 %0, {%1, %2};" : "=l"(r) : "f"(x), "f"(y)); return r;
}
__device__ __forceinline__ u64 ffma2(u64 a, u64 b, u64 c) {
    u64 d; asm("fma.rn.f32x2 %0, %1, %2, %3;" : "=l"(d) : "l"(a), "l"(b), "l"(c)); return d;
}
__device__ __forceinline__ float2 unpack2(u64 v) {
    float2 f; asm("mov.b64 {%0, %1}, %2;" : "=f"(f.x), "=f"(f.y) : "l"(v)); return f;
}

// ---------------- init ----------------
__global__ void init_kernel() {
    int t = threadIdx.x;
    if (t < NEXP) { g_imp[t] = 0.f; g_load[t] = 0; g_cnt[t] = 0; }
    if (t == NEXP) g_z2 = 0.f;
}

// ---------------- router: logits, softmax, top-2, aux stats ----------------
__global__ void router_kernel(const float* __restrict__ x, const float* __restrict__ wr) {
    int n = blockIdx.x;
    int tid = threadIdx.x;
    int w = tid >> 5, lane = tid & 31;
    const float* xr = x + (size_t)n * HDIM;
    const float* we = wr + (size_t)w * HDIM;
    float s = 0.f;
    for (int j = lane; j < HDIM; j += 32) s += xr[j] * we[j];
    #pragma unroll
    for (int o = 16; o; o >>= 1) s += __shfl_xor_sync(0xffffffffu, s, o);
    __shared__ float lg[NEXP];
    if (lane == 0) lg[w] = s;
    __syncthreads();
    if (tid == 0) {
        float l[NEXP], p[NEXP];
        float m = -1e30f;
        #pragma unroll
        for (int e = 0; e < NEXP; e++) { l[e] = lg[e]; m = fmaxf(m, l[e]); }
        float se = 0.f;
        #pragma unroll
        for (int e = 0; e < NEXP; e++) { p[e] = expf(l[e] - m); se += p[e]; }
        float inv = 1.f / se;
        #pragma unroll
        for (int e = 0; e < NEXP; e++) { p[e] *= inv; atomicAdd(&g_imp[e], p[e]); }
        float z = m + logf(se);
        atomicAdd(&g_z2, z * z);
        // top-2, first-occurrence tie-break (matches jax.lax.top_k)
        int i1 = 0;
        #pragma unroll
        for (int e = 1; e < NEXP; e++) if (p[e] > p[i1]) i1 = e;
        int i2 = -1;
        #pragma unroll
        for (int e = 0; e < NEXP; e++) {
            if (e == i1) continue;
            if (i2 < 0 || p[e] > p[i2]) i2 = e;
        }
        float denom = p[i1] + p[i2] + 1e-9f;
        g_tokw[n * 2 + 0] = p[i1] / denom;
        g_tokw[n * 2 + 1] = p[i2] / denom;
        atomicAdd(&g_load[i1], 1);
        atomicAdd(&g_cnt[i1], 1);
        atomicAdd(&g_cnt[i2], 1);
        g_tokpos[n * 2 + 0] = i1;
        g_tokpos[n * 2 + 1] = i2;
    }
}

__global__ void prefix_kernel() {
    int o = 0;
    for (int e = 0; e < NEXP; e++) { g_off[e] = o; o += g_cnt[e]; g_cur[e] = 0; }
}

__global__ void scatter_kernel() {
    int n = blockIdx.x * blockDim.x + threadIdx.x;
    if (n < NTOK) {
        #pragma unroll
        for (int k = 0; k < 2; k++) {
            int e = g_tokpos[n * 2 + k];
            int p = g_off[e] + atomicAdd(&g_cur[e], 1);
            g_rowtok[p] = n;
            g_tokpos[n * 2 + k] = p;
        }
        g_rowtok[NROWS_ROUTED + n] = n; // shared-expert group rows
    }
}

// ---------------- grouped GEMMs (FFMA2), B-tile register prefetch ----------------
#define BM 128
#define BN 64
#define BK 16

// Fused gate+up: act[r][f] = silu(A[r].Wg[e][f]) * (A[r].Wu[e][f]), K = HDIM
__global__ void __launch_bounds__(256, 2)
gemm_gu_kernel(const float* __restrict__ x,
               const float* __restrict__ weg, const float* __restrict__ wshg,
               const float* __restrict__ weu, const float* __restrict__ wshu) {
    const int g = blockIdx.y;
    int off, cnt;
    if (g < NEXP) { off = g_off[g]; cnt = g_cnt[g]; }
    else          { off = NROWS_ROUTED; cnt = NTOK; }
    const int row0 = blockIdx.x * BM;
    if (row0 >= cnt) return;

    const float* Bg = (g < NEXP) ? (weg + (size_t)g * ((size_t)FDIM * HDIM)) : wshg;
    const float* Bu = (g < NEXP) ? (weu + (size_t)g * ((size_t)FDIM * HDIM)) : wshu;
    const int n0 = blockIdx.z * BN;

    __shared__ float As [BK][BM + 4];
    __shared__ float Bgs[BK][BN + 4];
    __shared__ float Bus[BK][BN + 4];
    __shared__ const float* Arow[BM];

    const int tid = threadIdx.x;
    if (tid < BM) {
        int r = row0 + tid;
        int rc = (r < cnt) ? r : (cnt - 1);
        Arow[tid] = x + (size_t)g_rowtok[off + rc] * HDIM;
    }
    __syncthreads();

    u64 accg[8][2], accu[8][2];
    #pragma unroll
    for (int i = 0; i < 8; i++) { accg[i][0] = accg[i][1] = 0ull; accu[i][0] = accu[i][1] = 0ull; }

    const int tr = tid >> 4, tc = tid & 15;
    const int lm = tid >> 2, lk = tid & 3;      // A-load: row lm, k-quad lk
    const int bn = tid >> 2, bk = tid & 3;      // B-load: col bn, k-quad bk

    const float* aptr0 = Arow[lm]      + lk * 4;
    const float* aptr1 = Arow[lm + 64] + lk * 4;
    const float* bgp = Bg + (size_t)(n0 + bn) * HDIM + bk * 4;
    const float* bup = Bu + (size_t)(n0 + bn) * HDIM + bk * 4;

    // prefetch first B tiles (weights stream from DRAM; x-rows stay L2-hot)
    float4 pg = *(const float4*)(bgp);
    float4 pu = *(const float4*)(bup);

    for (int kt = 0; kt < HDIM; kt += BK) {
        {
            float4 v = *(const float4*)(aptr0 + kt);
            As[lk * 4 + 0][lm] = v.x; As[lk * 4 + 1][lm] = v.y;
            As[lk * 4 + 2][lm] = v.z; As[lk * 4 + 3][lm] = v.w;
            float4 w = *(const float4*)(aptr1 + kt);
            As[lk * 4 + 0][lm + 64] = w.x; As[lk * 4 + 1][lm + 64] = w.y;
            As[lk * 4 + 2][lm + 64] = w.z; As[lk * 4 + 3][lm + 64] = w.w;
            Bgs[bk * 4 + 0][bn] = pg.x; Bgs[bk * 4 + 1][bn] = pg.y;
            Bgs[bk * 4 + 2][bn] = pg.z; Bgs[bk * 4 + 3][bn] = pg.w;
            Bus[bk * 4 + 0][bn] = pu.x; Bus[bk * 4 + 1][bn] = pu.y;
            Bus[bk * 4 + 2][bn] = pu.z; Bus[bk * 4 + 3][bn] = pu.w;
        }
        __syncthreads();
        if (kt + BK < HDIM) {   // issue next B loads; latency overlapped by compute
            pg = *(const float4*)(bgp + kt + BK);
            pu = *(const float4*)(bup + kt + BK);
        }
        #pragma unroll
        for (int kk = 0; kk < BK; kk++) {
            float4 a0 = *(const float4*)&As[kk][tr * 8];
            float4 a1 = *(const float4*)&As[kk][tr * 8 + 4];
            ulonglong2 bg2 = *(const ulonglong2*)&Bgs[kk][tc * 4];
            ulonglong2 bu2 = *(const ulonglong2*)&Bus[kk][tc * 4];
            u64 a2[8];
            a2[0] = pack2(a0.x, a0.x); a2[1] = pack2(a0.y, a0.y);
            a2[2] = pack2(a0.z, a0.z); a2[3] = pack2(a0.w, a0.w);
            a2[4] = pack2(a1.x, a1.x); a2[5] = pack2(a1.y, a1.y);
            a2[6] = pack2(a1.z, a1.z); a2[7] = pack2(a1.w, a1.w);
            #pragma unroll
            for (int i = 0; i < 8; i++) {
                accg[i][0] = ffma2(a2[i], bg2.x, accg[i][0]);
                accg[i][1] = ffma2(a2[i], bg2.y, accg[i][1]);
                accu[i][0] = ffma2(a2[i], bu2.x, accu[i][0]);
                accu[i][1] = ffma2(a2[i], bu2.y, accu[i][1]);
            }
        }
        __syncthreads();
    }

    #pragma unroll
    for (int i = 0; i < 8; i++) {
        int r = row0 + tr * 8 + i;
        if (r < cnt) {
            float* o = g_act + (size_t)(off + r) * FDIM + n0 + tc * 4;
            #pragma unroll
            for (int jp = 0; jp < 2; jp++) {
                float2 gg = unpack2(accg[i][jp]);
                float2 uu = unpack2(accu[i][jp]);
                o[jp * 2 + 0] = (gg.x / (1.f + __expf(-gg.x))) * uu.x;
                o[jp * 2 + 1] = (gg.y / (1.f + __expf(-gg.y))) * uu.y;
            }
        }
    }
}

// Down: y[r][h] = act[r] . Wd[e][h], K = FDIM. Prefetch A and B.
__global__ void __launch_bounds__(256, 2)
gemm_down_kernel(const float* __restrict__ wed, const float* __restrict__ wshd) {
    const int g = blockIdx.y;
    int off, cnt;
    if (g < NEXP) { off = g_off[g]; cnt = g_cnt[g]; }
    else          { off = NROWS_ROUTED; cnt = NTOK; }
    const int row0 = blockIdx.x * BM;
    if (row0 >= cnt) return;

    const float* Bp = (g < NEXP) ? (wed + (size_t)g * ((size_t)HDIM * FDIM)) : wshd;
    const int n0 = blockIdx.z * BN;

    __shared__ float As[BK][BM + 4];
    __shared__ float Bs[BK][BN + 4];

    const int tid = threadIdx.x;
    const int tr = tid >> 4, tc = tid & 15;
    const int lm = tid >> 2, lk = tid & 3;
    const int bn = tid >> 2, bk = tid & 3;

    const int rA  = (row0 + lm      < cnt) ? (row0 + lm)      : (cnt - 1);
    const int rA1 = (row0 + lm + 64 < cnt) ? (row0 + lm + 64) : (cnt - 1);
    const float* a_base0 = g_act + (size_t)(off + rA)  * FDIM + lk * 4;
    const float* a_base1 = g_act + (size_t)(off + rA1) * FDIM + lk * 4;
    const float* b_base  = Bp + (size_t)(n0 + bn) * FDIM + bk * 4;

    u64 acc[8][2];
    #pragma unroll
    for (int i = 0; i < 8; i++) { acc[i][0] = 0ull; acc[i][1] = 0ull; }

    float4 p0 = *(const float4*)(a_base0);
    float4 p1 = *(const float4*)(a_base1);
    float4 pb = *(const float4*)(b_base);

    for (int kt = 0; kt < FDIM; kt += BK) {
        {
            As[lk * 4 + 0][lm] = p0.x; As[lk * 4 + 1][lm] = p0.y;
            As[lk * 4 + 2][lm] = p0.z; As[lk * 4 + 3][lm] = p0.w;
            As[lk * 4 + 0][lm + 64] = p1.x; As[lk * 4 + 1][lm + 64] = p1.y;
            As[lk * 4 + 2][lm + 64] = p1.z; As[lk * 4 + 3][lm + 64] = p1.w;
            Bs[bk * 4 + 0][bn] = pb.x; Bs[bk * 4 + 1][bn] = pb.y;
            Bs[bk * 4 + 2][bn] = pb.z; Bs[bk * 4 + 3][bn] = pb.w;
        }
        __syncthreads();
        if (kt + BK < FDIM) {
            p0 = *(const float4*)(a_base0 + kt + BK);
            p1 = *(const float4*)(a_base1 + kt + BK);
            pb = *(const float4*)(b_base + kt + BK);
        }
        #pragma unroll
        for (int kk = 0; kk < BK; kk++) {
            float4 a0 = *(const float4*)&As[kk][tr * 8];
            float4 a1 = *(const float4*)&As[kk][tr * 8 + 4];
            ulonglong2 b2 = *(const ulonglong2*)&Bs[kk][tc * 4];
            u64 a2[8];
            a2[0] = pack2(a0.x, a0.x); a2[1] = pack2(a0.y, a0.y);
            a2[2] = pack2(a0.z, a0.z); a2[3] = pack2(a0.w, a0.w);
            a2[4] = pack2(a1.x, a1.x); a2[5] = pack2(a1.y, a1.y);
            a2[6] = pack2(a1.z, a1.z); a2[7] = pack2(a1.w, a1.w);
            #pragma unroll
            for (int i = 0; i < 8; i++) {
                acc[i][0] = ffma2(a2[i], b2.x, acc[i][0]);
                acc[i][1] = ffma2(a2[i], b2.y, acc[i][1]);
            }
        }
        __syncthreads();
    }

    #pragma unroll
    for (int i = 0; i < 8; i++) {
        int r = row0 + tr * 8 + i;
        if (r < cnt) {
            float* o = g_y + (size_t)(off + r) * HDIM + n0 + tc * 4;
            float2 v0 = unpack2(acc[i][0]);
            float2 v1 = unpack2(acc[i][1]);
            o[0] = v0.x; o[1] = v0.y; o[2] = v1.x; o[3] = v1.y;
        }
    }
}

// ---------------- combine: y = shared + w0*e0 + w1*e1 ----------------
__global__ void combine_kernel(float* __restrict__ out) {
    int n = blockIdx.x;
    int p0 = g_tokpos[n * 2], p1 = g_tokpos[n * 2 + 1];
    float w0 = g_tokw[n * 2], w1 = g_tokw[n * 2 + 1];
    const float4* ysh = (const float4*)(g_y + (size_t)(NROWS_ROUTED + n) * HDIM);
    const float4* y0  = (const float4*)(g_y + (size_t)p0 * HDIM);
    const float4* y1  = (const float4*)(g_y + (size_t)p1 * HDIM);
    float4* o = (float4*)(out + (size_t)n * HDIM);
    for (int h = threadIdx.x; h < HDIM / 4; h += blockDim.x) {
        float4 s = ysh[h], a = y0[h], b = y1[h], rr;
        rr.x = s.x + w0 * a.x + w1 * b.x;
        rr.y = s.y + w0 * a.y + w1 * b.y;
        rr.z = s.z + w0 * a.z + w1 * b.z;
        rr.w = s.w + w0 * a.w + w1 * b.w;
        o[h] = rr;
    }
}

// ---------------- aux losses ----------------
__global__ void aux_kernel(float* __restrict__ out, int out_size) {
    const int yelems = NTOK * HDIM;
    if (out_size <= yelems) return;
    float imp[NEXP], ld[NEXP];
    float impSum = 0.f, loadSum = 0.f;
    for (int e = 0; e < NEXP; e++) {
        imp[e] = g_imp[e]; ld[e] = (float)g_load[e];
        impSum += imp[e]; loadSum += ld[e];
    }
    float lb = 0.f;
    for (int e = 0; e < NEXP; e++)
        lb += (imp[e] / (impSum + 1e-9f)) * (ld[e] / (loadSum + 1e-9f));
    lb *= (float)NEXP;
    float z_loss = 0.001f * (g_z2 / (float)NTOK);
    out[yelems] = 0.01f * lb + z_loss;
    for (int i = yelems + 1; i < out_size; i++) out[i] = 0.f;
}

// ---------------- launch ----------------
extern "C" void kernel_launch(void* const* d_in, const int* in_sizes, int n_in,
                              void* d_out, int out_size) {
    const float* x    = (const float*)d_in[0];
    const float* wr   = (const float*)d_in[1];
    const float* wshg = (const float*)d_in[2];
    const float* wshu = (const float*)d_in[3];
    const float* wshd = (const float*)d_in[4];
    const float* weg  = (const float*)d_in[5];
    const float* weu  = (const float*)d_in[6];
    const float* wed  = (const float*)d_in[7];
    float* out = (float*)d_out;

    init_kernel<<<1, 32>>>();
    router_kernel<<<NTOK, 256>>>(x, wr);
    prefix_kernel<<<1, 1>>>();
    scatter_kernel<<<16, 256>>>();

    dim3 gGU(NROWS_ROUTED / BM, NGRP, FDIM / BN);  // (64, 9, 32)
    gemm_gu_kernel<<<gGU, 256>>>(x, weg, wshg, weu, wshu);
    dim3 gD(NROWS_ROUTED / BM, NGRP, HDIM / BN);   // (64, 9, 16)
    gemm_down_kernel<<<gD, 256>>>(wed, wshd);

    combine_kernel<<<NTOK, 256>>>(out);
    aux_kernel<<<1, 1>>>(out, out_size);
}